// round 2
// baseline (speedup 1.0000x reference)
#include <cuda_runtime.h>
#include <cfloat>
#include <math.h>

#define B_   16
#define NPER 2048
#define NTOT (B_*NPER)
#define KNN  20

// ---------------- scratch (device globals; no runtime allocation) ----------
__device__ float4 g_x0[NTOT];            // [N][4]  concat(pos, x)
__device__ int    g_idx[NTOT*KNN];       // [N][20] global neighbor indices
__device__ float  g_x1[NTOT*64];
__device__ float  g_x2[NTOT*64];
__device__ float  g_x3[NTOT*128];
__device__ float  g_out2[B_*1024];       // global max pool result

__device__ __forceinline__ void atomicMaxFloat(float* addr, float v){
    if (v >= 0.f) atomicMax((int*)addr, __float_as_int(v));
    else          atomicMin((unsigned int*)addr, (unsigned int)__float_as_int(v));
}

// ---------------- kNN: one thread per query, register top-20 ---------------
__global__ __launch_bounds__(128) void knn_kernel(const float* __restrict__ pos,
                                                  const float* __restrict__ xf)
{
    __shared__ float4 sp[NPER];
    __shared__ float  sn[NPER];
    int b     = blockIdx.x >> 4;
    int qbase = (blockIdx.x & 15) << 7;
    int base  = b * NPER;
    for (int j = threadIdx.x; j < NPER; j += 128){
        float px = pos[(base+j)*3+0];
        float py = pos[(base+j)*3+1];
        float pz = pos[(base+j)*3+2];
        float pw = xf[base+j];
        float4 p = make_float4(px,py,pz,pw);
        sp[j] = p;
        sn[j] = px*px + py*py + pz*pz + pw*pw;
        if ((blockIdx.x & 15) == 0) g_x0[base+j] = p;   // write x0 once per graph
    }
    __syncthreads();

    int q = qbase + (int)threadIdx.x;
    float4 p = sp[q];
    float  pn = sn[q];
    float bd[KNN]; int bi[KNN];
    #pragma unroll
    for (int t=0;t<KNN;t++){ bd[t]=FLT_MAX; bi[t]=0; }
    float worst = FLT_MAX; int ws = 0;

    for (int j=0;j<NPER;j+=4){
        float d[4];
        #pragma unroll
        for (int u=0;u<4;u++){
            float4 c = sp[j+u];
            d[u] = pn + sn[j+u] - 2.f*(p.x*c.x + p.y*c.y + p.z*c.z + p.w*c.w);
            if (j+u == q) d[u] = FLT_MAX;
        }
        float dm = fminf(fminf(d[0],d[1]), fminf(d[2],d[3]));
        if (dm < worst){
            #pragma unroll
            for (int u=0;u<4;u++){
                if (d[u] < worst){
                    // predicated register insert (no dynamic indexing)
                    #pragma unroll
                    for (int t=0;t<KNN;t++){
                        if (t == ws){ bd[t] = d[u]; bi[t] = j+u; }
                    }
                    // rescan for new worst
                    worst = bd[0]; ws = 0;
                    #pragma unroll
                    for (int t=1;t<KNN;t++){
                        if (bd[t] > worst){ worst = bd[t]; ws = t; }
                    }
                }
            }
        }
    }
    #pragma unroll
    for (int t=0;t<KNN;t++) g_idx[(base+q)*KNN + t] = base + bi[t];
}

// ---------------- EdgeConv1: fused MLP(8->64->64->64), max over K ----------
// 8 nodes per block (one per warp); single shared h-buffer reused for h1/h2
__global__ __launch_bounds__(256) void conv1_kernel(
    const float* __restrict__ w1, const float* __restrict__ b1,
    const float* __restrict__ w2, const float* __restrict__ b2,
    const float* __restrict__ w3, const float* __restrict__ b3)
{
    __shared__ float sW1 [4*64];     // bottom rows of w1
    __shared__ float sW1d[4*64];     // top - bottom
    __shared__ float sW2t[64*68];    // transposed, padded (conflict-free LDS.128)
    __shared__ float sW3t[64*68];
    __shared__ float sb1[64], sb2[64], sb3[64];
    __shared__ float hbuf[8][4][64];

    for (int t = threadIdx.x; t < 64*64; t += 256){
        int c = t >> 6, o = t & 63;
        sW2t[o*68+c] = w2[t];
        sW3t[o*68+c] = w3[t];
    }
    for (int t = threadIdx.x; t < 4*64; t += 256){
        int c = t >> 6, o = t & 63;
        float top = w1[c*64+o], bot = w1[(c+4)*64+o];
        sW1[t] = bot; sW1d[t] = top - bot;
    }
    if (threadIdx.x < 64){
        sb1[threadIdx.x] = b1[threadIdx.x];
        sb2[threadIdx.x] = b2[threadIdx.x];
        sb3[threadIdx.x] = b3[threadIdx.x];
    }
    __syncthreads();

    int wd = threadIdx.x >> 5, lane = threadIdx.x & 31;
    int i  = blockIdx.x * 8 + wd;
    int o0 = lane, o1 = lane + 32;
    float4 xi = g_x0[i];
    float base0 = sb1[o0] + xi.x*sW1d[o0] + xi.y*sW1d[64+o0] + xi.z*sW1d[128+o0] + xi.w*sW1d[192+o0];
    float base1 = sb1[o1] + xi.x*sW1d[o1] + xi.y*sW1d[64+o1] + xi.z*sW1d[128+o1] + xi.w*sW1d[192+o1];
    float mx0 = -FLT_MAX, mx1 = -FLT_MAX;
    const int* ip = g_idx + i*KNN;

    for (int kg = 0; kg < 5; kg++){
        #pragma unroll
        for (int e=0;e<4;e++){
            int j = ip[kg*4+e];
            float4 xj = g_x0[j];
            float v0 = base0 + xj.x*sW1[o0] + xj.y*sW1[64+o0] + xj.z*sW1[128+o0] + xj.w*sW1[192+o0];
            float v1 = base1 + xj.x*sW1[o1] + xj.y*sW1[64+o1] + xj.z*sW1[128+o1] + xj.w*sW1[192+o1];
            hbuf[wd][e][o0] = fmaxf(v0, 0.f);
            hbuf[wd][e][o1] = fmaxf(v1, 0.f);
        }
        __syncwarp();
        float a0[4], a1[4];
        #pragma unroll
        for (int e=0;e<4;e++){ a0[e]=sb2[o0]; a1[e]=sb2[o1]; }
        #pragma unroll
        for (int c4=0;c4<16;c4++){
            float4 wv0 = *(const float4*)(sW2t + o0*68 + c4*4);
            float4 wv1 = *(const float4*)(sW2t + o1*68 + c4*4);
            #pragma unroll
            for (int e=0;e<4;e++){
                float4 h = *(const float4*)(&hbuf[wd][e][c4*4]);
                a0[e] += h.x*wv0.x + h.y*wv0.y + h.z*wv0.z + h.w*wv0.w;
                a1[e] += h.x*wv1.x + h.y*wv1.y + h.z*wv1.z + h.w*wv1.w;
            }
        }
        __syncwarp();
        #pragma unroll
        for (int e=0;e<4;e++){
            hbuf[wd][e][o0] = fmaxf(a0[e], 0.f);
            hbuf[wd][e][o1] = fmaxf(a1[e], 0.f);
        }
        __syncwarp();
        #pragma unroll
        for (int e=0;e<4;e++){ a0[e]=sb3[o0]; a1[e]=sb3[o1]; }
        #pragma unroll
        for (int c4=0;c4<16;c4++){
            float4 wv0 = *(const float4*)(sW3t + o0*68 + c4*4);
            float4 wv1 = *(const float4*)(sW3t + o1*68 + c4*4);
            #pragma unroll
            for (int e=0;e<4;e++){
                float4 h = *(const float4*)(&hbuf[wd][e][c4*4]);
                a0[e] += h.x*wv0.x + h.y*wv0.y + h.z*wv0.z + h.w*wv0.w;
                a1[e] += h.x*wv1.x + h.y*wv1.y + h.z*wv1.z + h.w*wv1.w;
            }
        }
        #pragma unroll
        for (int e=0;e<4;e++){ mx0 = fmaxf(mx0, a0[e]); mx1 = fmaxf(mx1, a1[e]); }
        __syncwarp();
    }
    g_x1[i*64+o0] = mx0;
    g_x1[i*64+o1] = mx1;
}

// ---------------- EdgeConv2: 128->64 single layer, max over K --------------
__global__ __launch_bounds__(256) void conv2_kernel(
    const float* __restrict__ w, const float* __restrict__ bias)
{
    __shared__ float sWtt[64*68], sWbt[64*68];
    __shared__ float sb[64];
    __shared__ float xjbuf[8][4][64];
    __shared__ float xibuf[8][64];
    for (int t = threadIdx.x; t < 64*64; t += 256){
        int c = t >> 6, o = t & 63;
        sWtt[o*68+c] = w[t];
        sWbt[o*68+c] = w[4096 + t];
    }
    if (threadIdx.x < 64) sb[threadIdx.x] = bias[threadIdx.x];
    __syncthreads();

    int wd = threadIdx.x >> 5, lane = threadIdx.x & 31;
    int i  = blockIdx.x*8 + wd;
    int o0 = lane, o1 = lane+32;
    xibuf[wd][o0] = g_x1[i*64+o0];
    xibuf[wd][o1] = g_x1[i*64+o1];
    __syncwarp();
    float base0 = sb[o0], base1 = sb[o1];
    #pragma unroll
    for (int c4=0;c4<16;c4++){
        float4 x4  = *(const float4*)(&xibuf[wd][c4*4]);
        float4 wt0 = *(const float4*)(sWtt + o0*68 + c4*4);
        float4 wb0 = *(const float4*)(sWbt + o0*68 + c4*4);
        float4 wt1 = *(const float4*)(sWtt + o1*68 + c4*4);
        float4 wb1 = *(const float4*)(sWbt + o1*68 + c4*4);
        base0 += x4.x*(wt0.x-wb0.x) + x4.y*(wt0.y-wb0.y) + x4.z*(wt0.z-wb0.z) + x4.w*(wt0.w-wb0.w);
        base1 += x4.x*(wt1.x-wb1.x) + x4.y*(wt1.y-wb1.y) + x4.z*(wt1.z-wb1.z) + x4.w*(wt1.w-wb1.w);
    }
    float mx0=-FLT_MAX, mx1=-FLT_MAX;
    const int* ip = g_idx + i*KNN;
    for (int kg=0;kg<5;kg++){
        #pragma unroll
        for (int e=0;e<4;e++){
            int j = ip[kg*4+e];
            xjbuf[wd][e][o0] = g_x1[j*64+o0];
            xjbuf[wd][e][o1] = g_x1[j*64+o1];
        }
        __syncwarp();
        float a0[4], a1[4];
        #pragma unroll
        for (int e=0;e<4;e++){ a0[e]=base0; a1[e]=base1; }
        #pragma unroll
        for (int c4=0;c4<16;c4++){
            float4 wv0 = *(const float4*)(sWbt + o0*68 + c4*4);
            float4 wv1 = *(const float4*)(sWbt + o1*68 + c4*4);
            #pragma unroll
            for (int e=0;e<4;e++){
                float4 h = *(const float4*)(&xjbuf[wd][e][c4*4]);
                a0[e] += h.x*wv0.x + h.y*wv0.y + h.z*wv0.z + h.w*wv0.w;
                a1[e] += h.x*wv1.x + h.y*wv1.y + h.z*wv1.z + h.w*wv1.w;
            }
        }
        #pragma unroll
        for (int e=0;e<4;e++){ mx0=fmaxf(mx0,a0[e]); mx1=fmaxf(mx1,a1[e]); }
        __syncwarp();
    }
    g_x2[i*64+o0]=mx0; g_x2[i*64+o1]=mx1;
}

// ---------------- EdgeConv3: 128->128 single layer, max over K -------------
__global__ __launch_bounds__(256) void conv3_kernel(
    const float* __restrict__ w, const float* __restrict__ bias)
{
    __shared__ float sWbt[128*68];
    __shared__ float sb[128];
    __shared__ float xjbuf[8][4][64];
    __shared__ float xibuf[8][64];
    for (int t = threadIdx.x; t < 64*128; t += 256){
        int c = t >> 7, o = t & 127;
        sWbt[o*68+c] = w[(64+c)*128 + o];
    }
    if (threadIdx.x < 128) sb[threadIdx.x] = bias[threadIdx.x];
    __syncthreads();

    int wd = threadIdx.x >> 5, lane = threadIdx.x & 31;
    int i  = blockIdx.x*8 + wd;
    xibuf[wd][lane]    = g_x2[i*64+lane];
    xibuf[wd][lane+32] = g_x2[i*64+lane+32];
    __syncwarp();
    float base[4];
    #pragma unroll
    for (int oo=0;oo<4;oo++) base[oo] = sb[lane+32*oo];
    for (int c4=0;c4<16;c4++){
        float4 x4 = *(const float4*)(&xibuf[wd][c4*4]);
        #pragma unroll
        for (int oo=0;oo<4;oo++){
            int o = lane+32*oo;
            float4 wb = *(const float4*)(sWbt + o*68 + c4*4);
            float t0 = __ldg(&w[(c4*4+0)*128+o]);
            float t1 = __ldg(&w[(c4*4+1)*128+o]);
            float t2 = __ldg(&w[(c4*4+2)*128+o]);
            float t3 = __ldg(&w[(c4*4+3)*128+o]);
            base[oo] += x4.x*(t0-wb.x) + x4.y*(t1-wb.y) + x4.z*(t2-wb.z) + x4.w*(t3-wb.w);
        }
    }
    float mx[4] = {-FLT_MAX,-FLT_MAX,-FLT_MAX,-FLT_MAX};
    const int* ip = g_idx + i*KNN;
    for (int kg=0;kg<5;kg++){
        #pragma unroll
        for (int e=0;e<4;e++){
            int j = ip[kg*4+e];
            xjbuf[wd][e][lane]    = g_x2[j*64+lane];
            xjbuf[wd][e][lane+32] = g_x2[j*64+lane+32];
        }
        __syncwarp();
        float acc[4][4];
        #pragma unroll
        for (int e=0;e<4;e++)
            #pragma unroll
            for (int oo=0;oo<4;oo++) acc[e][oo]=base[oo];
        for (int c4=0;c4<16;c4++){
            float4 wv[4];
            #pragma unroll
            for (int oo=0;oo<4;oo++) wv[oo] = *(const float4*)(sWbt + (lane+32*oo)*68 + c4*4);
            #pragma unroll
            for (int e=0;e<4;e++){
                float4 h = *(const float4*)(&xjbuf[wd][e][c4*4]);
                #pragma unroll
                for (int oo=0;oo<4;oo++)
                    acc[e][oo] += h.x*wv[oo].x + h.y*wv[oo].y + h.z*wv[oo].z + h.w*wv[oo].w;
            }
        }
        #pragma unroll
        for (int e=0;e<4;e++)
            #pragma unroll
            for (int oo=0;oo<4;oo++) mx[oo] = fmaxf(mx[oo], acc[e][oo]);
        __syncwarp();
    }
    #pragma unroll
    for (int oo=0;oo<4;oo++) g_x3[i*128 + lane + 32*oo] = mx[oo];
}

// ---------------- init pool buffer ------------------------------------------
__global__ void init_out2_kernel(){
    int t = blockIdx.x*blockDim.x + threadIdx.x;
    if (t < B_*1024) g_out2[t] = -FLT_MAX;
}

// ---------------- lin1 (256->1024) fused with global max pool --------------
// conflict-free mappings: node n = tn + 16*r (fbuf stride 33, odd),
//                         out  o = to + 16*q (wbuf: 16 distinct banks)
__global__ __launch_bounds__(256) void lin1max_kernel(
    const float* __restrict__ l1w, const float* __restrict__ l1b)
{
    __shared__ float fbuf[64*33];
    __shared__ float wbuf[32*132];
    int g     = blockIdx.x >> 5;
    int nbase = g*NPER + (blockIdx.x & 31)*64;
    int tn = threadIdx.x & 15, to = threadIdx.x >> 4;

    for (int oc=0; oc<8; ++oc){
        float acc[4][8];
        #pragma unroll
        for (int r=0;r<4;r++)
            #pragma unroll
            for (int q=0;q<8;q++) acc[r][q]=0.f;

        for (int kc=0;kc<8;kc++){
            for (int t=threadIdx.x; t<64*32; t+=256){
                int n = t>>5, kk = t&31;
                int kglob = kc*32+kk;
                int node  = nbase + n;
                float v;
                if (kglob < 64)       v = g_x1[node*64  + kglob];
                else if (kglob < 128) v = g_x2[node*64  + (kglob-64)];
                else                  v = g_x3[node*128 + (kglob-128)];
                fbuf[n*33+kk] = v;
            }
            for (int t=threadIdx.x; t<32*128; t+=256){
                int kk = t>>7, o = t&127;
                wbuf[kk*132+o] = l1w[(kc*32+kk)*1024 + oc*128 + o];
            }
            __syncthreads();
            #pragma unroll 4
            for (int kk=0;kk<32;kk++){
                float f0 = fbuf[(tn +  0)*33+kk];
                float f1 = fbuf[(tn + 16)*33+kk];
                float f2 = fbuf[(tn + 32)*33+kk];
                float f3 = fbuf[(tn + 48)*33+kk];
                float wv[8];
                #pragma unroll
                for (int q=0;q<8;q++) wv[q] = wbuf[kk*132 + to + 16*q];
                #pragma unroll
                for (int q=0;q<8;q++){
                    acc[0][q] += f0*wv[q];
                    acc[1][q] += f1*wv[q];
                    acc[2][q] += f2*wv[q];
                    acc[3][q] += f3*wv[q];
                }
            }
            __syncthreads();
        }
        float m[8];
        #pragma unroll
        for (int q=0;q<8;q++)
            m[q] = fmaxf(fmaxf(acc[0][q],acc[1][q]), fmaxf(acc[2][q],acc[3][q]));
        // cross-tn reduction: column c = to + 16*q  (matches weight mapping)
        #pragma unroll
        for (int q=0;q<8;q++) wbuf[tn*128 + to + 16*q] = m[q];
        __syncthreads();
        if (threadIdx.x < 128){
            int c = threadIdx.x;
            float v = wbuf[c];
            #pragma unroll
            for (int t=1;t<16;t++) v = fmaxf(v, wbuf[t*128+c]);
            v += l1b[oc*128+c];
            atomicMaxFloat(&g_out2[g*1024 + oc*128 + c], v);
        }
        __syncthreads();
    }
}

// ---------------- head: MLP(1024->512->256->10) + log_softmax --------------
__global__ __launch_bounds__(256) void head_kernel(
    const float* __restrict__ m1w, const float* __restrict__ m1b,
    const float* __restrict__ m2w, const float* __restrict__ m2b,
    const float* __restrict__ m3w, const float* __restrict__ m3b,
    float* __restrict__ out)
{
    __shared__ float v[1024];
    __shared__ float h1[512];
    __shared__ float h2[256];
    __shared__ float z[10];
    int g = blockIdx.x;
    for (int t=threadIdx.x; t<1024; t+=256) v[t] = g_out2[g*1024+t];
    __syncthreads();
    #pragma unroll
    for (int oo=0;oo<2;oo++){
        int o = threadIdx.x + oo*256;
        float a = m1b[o];
        #pragma unroll 4
        for (int k=0;k<1024;k++) a += v[k]*m1w[k*512+o];
        h1[o] = fmaxf(a, 0.f);
    }
    __syncthreads();
    {
        int o = threadIdx.x;
        float a = m2b[o];
        #pragma unroll 4
        for (int k=0;k<512;k++) a += h1[k]*m2w[k*256+o];
        h2[o] = fmaxf(a, 0.f);
    }
    __syncthreads();
    if (threadIdx.x < 10){
        float a = m3b[threadIdx.x];
        for (int k=0;k<256;k++) a += h2[k]*m3w[k*10+threadIdx.x];
        z[threadIdx.x] = a;
    }
    __syncthreads();
    if (threadIdx.x == 0){
        float m = -FLT_MAX;
        for (int c=0;c<10;c++) m = fmaxf(m, z[c]);
        float s = 0.f;
        for (int c=0;c<10;c++) s += expf(z[c]-m);
        float l = logf(s);
        for (int c=0;c<10;c++) out[g*10+c] = z[c]-m-l;
    }
}

// ---------------- launch ----------------------------------------------------
extern "C" void kernel_launch(void* const* d_in, const int* in_sizes, int n_in,
                              void* d_out, int out_size)
{
    const float* pos  = (const float*)d_in[0];
    const float* xf   = (const float*)d_in[1];
    // d_in[2] = batch (implied by layout, unused)
    const float* c1w1 = (const float*)d_in[3];
    const float* c1b1 = (const float*)d_in[4];
    const float* c1w2 = (const float*)d_in[5];
    const float* c1b2 = (const float*)d_in[6];
    const float* c1w3 = (const float*)d_in[7];
    const float* c1b3 = (const float*)d_in[8];
    const float* c2w  = (const float*)d_in[9];
    const float* c2b  = (const float*)d_in[10];
    const float* c3w  = (const float*)d_in[11];
    const float* c3b  = (const float*)d_in[12];
    const float* l1w  = (const float*)d_in[13];
    const float* l1b  = (const float*)d_in[14];
    const float* m1w  = (const float*)d_in[15];
    const float* m1b  = (const float*)d_in[16];
    const float* m2w  = (const float*)d_in[17];
    const float* m2b  = (const float*)d_in[18];
    const float* m3w  = (const float*)d_in[19];
    const float* m3b  = (const float*)d_in[20];
    float* out = (float*)d_out;

    knn_kernel<<<B_*16, 128>>>(pos, xf);
    conv1_kernel<<<NTOT/8, 256>>>(c1w1,c1b1,c1w2,c1b2,c1w3,c1b3);
    conv2_kernel<<<NTOT/8, 256>>>(c2w, c2b);
    conv3_kernel<<<NTOT/8, 256>>>(c3w, c3b);
    init_out2_kernel<<<(B_*1024+255)/256, 256>>>();
    lin1max_kernel<<<B_*32, 256>>>(l1w, l1b);
    head_kernel<<<B_, 256>>>(m1w,m1b,m2w,m2b,m3w,m3b,out);
}

// round 4
// speedup vs baseline: 1.2275x; 1.2275x over previous
#include <cuda_runtime.h>
#include <cfloat>
#include <math.h>

#define B_   16
#define NPER 2048
#define NTOT (B_*NPER)
#define KNN  20

// ---------------- scratch (device globals; no runtime allocation) ----------
__device__ float4 g_x0[NTOT];            // [N][4]  concat(pos, x)
__device__ int    g_idx[NTOT*KNN];       // [N][20] global neighbor indices
__device__ float  g_x1[NTOT*64];
__device__ float  g_x2[NTOT*64];
__device__ float  g_x3[NTOT*128];
__device__ float  g_u2[NTOT*64];         // x1 @ (W2_top - W2_bot)
__device__ float  g_y2[NTOT*64];         // x1 @ W2_bot
__device__ float  g_u3[NTOT*128];        // x2 @ (W3_top - W3_bot)
__device__ float  g_y3[NTOT*128];        // x2 @ W3_bot
__device__ float  g_out2[B_*1024];       // global max pool result

__device__ __forceinline__ void atomicMaxFloat(float* addr, float v){
    if (v >= 0.f) atomicMax((int*)addr, __float_as_int(v));
    else          atomicMin((unsigned int*)addr, (unsigned int)__float_as_int(v));
}

// ---------------- kNN: one thread per query node (round-1 proven) ----------
__global__ __launch_bounds__(256) void knn_kernel(const float* __restrict__ pos,
                                                  const float* __restrict__ xf)
{
    __shared__ float4 sp[NPER];
    __shared__ float  sn[NPER];
    int b     = blockIdx.x >> 3;
    int qbase = (blockIdx.x & 7) << 8;
    int base  = b * NPER;
    for (int j = threadIdx.x; j < NPER; j += 256){
        float px = pos[(base+j)*3+0];
        float py = pos[(base+j)*3+1];
        float pz = pos[(base+j)*3+2];
        float pw = xf[base+j];
        float4 p = make_float4(px,py,pz,pw);
        sp[j] = p;
        sn[j] = px*px + py*py + pz*pz + pw*pw;
        if ((blockIdx.x & 7) == 0) g_x0[base+j] = p;   // write x0 once per graph
    }
    __syncthreads();

    int q = qbase + (int)threadIdx.x;
    float4 p = sp[q];
    float  pn = sn[q];
    float bd[KNN]; int bi[KNN];
    #pragma unroll
    for (int t=0;t<KNN;t++){ bd[t]=FLT_MAX; bi[t]=0; }
    float worst = FLT_MAX; int ws = 0;

    for (int j=0;j<NPER;j++){
        float4 c = sp[j];
        float d = pn + sn[j] - 2.f*(p.x*c.x + p.y*c.y + p.z*c.z + p.w*c.w);
        if (d < worst && j != q){
            bd[ws] = d; bi[ws] = j;
            worst = bd[0]; ws = 0;
            #pragma unroll
            for (int t=1;t<KNN;t++) if (bd[t] > worst){ worst = bd[t]; ws = t; }
        }
    }
    #pragma unroll
    for (int t=0;t<KNN;t++) g_idx[(base+q)*KNN + t] = base + bi[t];
}

// ---------------- EdgeConv1: fused MLP(8->64->64->64), max over K ----------
__global__ __launch_bounds__(256) void conv1_kernel(
    const float* __restrict__ w1, const float* __restrict__ b1,
    const float* __restrict__ w2, const float* __restrict__ b2,
    const float* __restrict__ w3, const float* __restrict__ b3)
{
    __shared__ float sW1 [4*64];     // bottom rows of w1
    __shared__ float sW1d[4*64];     // top - bottom
    __shared__ float sW2t[64*68];    // transposed, padded (conflict-free LDS.128)
    __shared__ float sW3t[64*68];
    __shared__ float sb1[64], sb2[64], sb3[64];
    __shared__ float hbuf[8][4][64];

    for (int t = threadIdx.x; t < 64*64; t += 256){
        int c = t >> 6, o = t & 63;
        sW2t[o*68+c] = w2[t];
        sW3t[o*68+c] = w3[t];
    }
    for (int t = threadIdx.x; t < 4*64; t += 256){
        int c = t >> 6, o = t & 63;
        float top = w1[c*64+o], bot = w1[(c+4)*64+o];
        sW1[t] = bot; sW1d[t] = top - bot;
    }
    if (threadIdx.x < 64){
        sb1[threadIdx.x] = b1[threadIdx.x];
        sb2[threadIdx.x] = b2[threadIdx.x];
        sb3[threadIdx.x] = b3[threadIdx.x];
    }
    __syncthreads();

    int wd = threadIdx.x >> 5, lane = threadIdx.x & 31;
    int i  = blockIdx.x * 8 + wd;
    int o0 = lane, o1 = lane + 32;
    float4 xi = g_x0[i];
    float base0 = sb1[o0] + xi.x*sW1d[o0] + xi.y*sW1d[64+o0] + xi.z*sW1d[128+o0] + xi.w*sW1d[192+o0];
    float base1 = sb1[o1] + xi.x*sW1d[o1] + xi.y*sW1d[64+o1] + xi.z*sW1d[128+o1] + xi.w*sW1d[192+o1];
    float mx0 = -FLT_MAX, mx1 = -FLT_MAX;
    const int* ip = g_idx + i*KNN;

    for (int kg = 0; kg < 5; kg++){
        #pragma unroll
        for (int e=0;e<4;e++){
            int j = ip[kg*4+e];
            float4 xj = g_x0[j];
            float v0 = base0 + xj.x*sW1[o0] + xj.y*sW1[64+o0] + xj.z*sW1[128+o0] + xj.w*sW1[192+o0];
            float v1 = base1 + xj.x*sW1[o1] + xj.y*sW1[64+o1] + xj.z*sW1[128+o1] + xj.w*sW1[192+o1];
            hbuf[wd][e][o0] = fmaxf(v0, 0.f);
            hbuf[wd][e][o1] = fmaxf(v1, 0.f);
        }
        __syncwarp();
        float a0[4], a1[4];
        #pragma unroll
        for (int e=0;e<4;e++){ a0[e]=sb2[o0]; a1[e]=sb2[o1]; }
        #pragma unroll
        for (int c4=0;c4<16;c4++){
            float4 wv0 = *(const float4*)(sW2t + o0*68 + c4*4);
            float4 wv1 = *(const float4*)(sW2t + o1*68 + c4*4);
            #pragma unroll
            for (int e=0;e<4;e++){
                float4 h = *(const float4*)(&hbuf[wd][e][c4*4]);
                a0[e] += h.x*wv0.x + h.y*wv0.y + h.z*wv0.z + h.w*wv0.w;
                a1[e] += h.x*wv1.x + h.y*wv1.y + h.z*wv1.z + h.w*wv1.w;
            }
        }
        __syncwarp();
        #pragma unroll
        for (int e=0;e<4;e++){
            hbuf[wd][e][o0] = fmaxf(a0[e], 0.f);
            hbuf[wd][e][o1] = fmaxf(a1[e], 0.f);
        }
        __syncwarp();
        #pragma unroll
        for (int e=0;e<4;e++){ a0[e]=sb3[o0]; a1[e]=sb3[o1]; }
        #pragma unroll
        for (int c4=0;c4<16;c4++){
            float4 wv0 = *(const float4*)(sW3t + o0*68 + c4*4);
            float4 wv1 = *(const float4*)(sW3t + o1*68 + c4*4);
            #pragma unroll
            for (int e=0;e<4;e++){
                float4 h = *(const float4*)(&hbuf[wd][e][c4*4]);
                a0[e] += h.x*wv0.x + h.y*wv0.y + h.z*wv0.z + h.w*wv0.w;
                a1[e] += h.x*wv1.x + h.y*wv1.y + h.z*wv1.z + h.w*wv1.w;
            }
        }
        #pragma unroll
        for (int e=0;e<4;e++){ mx0 = fmaxf(mx0, a0[e]); mx1 = fmaxf(mx1, a1[e]); }
        __syncwarp();
    }
    g_x1[i*64+o0] = mx0;
    g_x1[i*64+o1] = mx1;
}

// ---------------- node-level GEMM: [64 nodes] x [128 o'] tile, K=64 --------
// o' < OUT -> U = X@(W_top - W_bot); o' >= OUT -> Y = X@W_bot
__device__ __forceinline__ void uy_gemm_body(
    const float* __restrict__ X,   // [N x 64]
    const float* __restrict__ W,   // [128 x OUT] (input-dim major)
    float* __restrict__ U, float* __restrict__ Y, int OUT)
{
    __shared__ float fbuf[64*33];
    __shared__ float wbuf[32*132];
    int nbase = blockIdx.x * 64;
    int otile = blockIdx.y * 128;
    int tn = threadIdx.x & 15;   // output group
    int to = threadIdx.x >> 4;   // node group

    float acc[4][8];
    #pragma unroll
    for (int r=0;r<4;r++)
        #pragma unroll
        for (int q=0;q<8;q++) acc[r][q]=0.f;

    for (int kc=0;kc<2;kc++){
        for (int t=threadIdx.x; t<64*32; t+=256){
            int n=t>>5, kk=t&31;
            fbuf[n*33+kk] = X[(nbase+n)*64 + kc*32 + kk];
        }
        for (int t=threadIdx.x; t<32*128; t+=256){
            int kk=t>>7, oloc=t&127;
            int op = otile + oloc;
            int k  = kc*32+kk;
            // U half uses (W_top - W_bot); Y half uses W_bot
            wbuf[kk*132+oloc] = (op < OUT)
                ? (W[k*OUT + op] - W[(64+k)*OUT + op])
                : W[(64+k)*OUT + (op-OUT)];
        }
        __syncthreads();
        #pragma unroll 4
        for (int kk=0;kk<32;kk++){
            float f[4];
            #pragma unroll
            for (int r=0;r<4;r++) f[r] = fbuf[(to+16*r)*33+kk];
            float wv[8];
            #pragma unroll
            for (int q=0;q<8;q++) wv[q] = wbuf[kk*132 + tn + 16*q];
            #pragma unroll
            for (int r=0;r<4;r++)
                #pragma unroll
                for (int q=0;q<8;q++) acc[r][q] += f[r]*wv[q];
        }
        __syncthreads();
    }
    #pragma unroll
    for (int r=0;r<4;r++){
        int node = nbase + to + 16*r;
        #pragma unroll
        for (int q=0;q<8;q++){
            int op = otile + tn + 16*q;
            if (op < OUT) U[node*OUT + op]        = acc[r][q];
            else          Y[node*OUT + (op-OUT)]  = acc[r][q];
        }
    }
}

__global__ __launch_bounds__(256) void uy_gemm2_kernel(const float* __restrict__ W){
    uy_gemm_body(g_x1, W, g_u2, g_y2, 64);
}
__global__ __launch_bounds__(256) void uy_gemm3_kernel(const float* __restrict__ W){
    uy_gemm_body(g_x2, W, g_u3, g_y3, 128);
}

// ---------------- gather + elementwise max: x2 = b2 + u_i + max_j y_j ------
__global__ __launch_bounds__(256) void gathermax2_kernel(const float* __restrict__ b2){
    int wd = threadIdx.x >> 5, lane = threadIdx.x & 31;
    int i = blockIdx.x*8 + wd;
    const int* ip = g_idx + i*KNN;
    float2 mx = make_float2(-FLT_MAX, -FLT_MAX);
    #pragma unroll 5
    for (int t=0;t<KNN;t++){
        int j = ip[t];
        float2 v = *(const float2*)(g_y2 + j*64 + lane*2);
        mx.x = fmaxf(mx.x, v.x);
        mx.y = fmaxf(mx.y, v.y);
    }
    float2 u  = *(const float2*)(g_u2 + i*64 + lane*2);
    float2 bb = *(const float2*)(b2 + lane*2);
    float2 o;
    o.x = bb.x + u.x + mx.x;
    o.y = bb.y + u.y + mx.y;
    *(float2*)(g_x2 + i*64 + lane*2) = o;
}

// ---------------- gather + elementwise max: x3 = b3 + u_i + max_j y_j ------
__global__ __launch_bounds__(256) void gathermax3_kernel(const float* __restrict__ b3){
    int wd = threadIdx.x >> 5, lane = threadIdx.x & 31;
    int i = blockIdx.x*8 + wd;
    const int* ip = g_idx + i*KNN;
    float4 mx = make_float4(-FLT_MAX,-FLT_MAX,-FLT_MAX,-FLT_MAX);
    #pragma unroll 5
    for (int t=0;t<KNN;t++){
        int j = ip[t];
        float4 v = *(const float4*)(g_y3 + j*128 + lane*4);
        mx.x = fmaxf(mx.x, v.x);
        mx.y = fmaxf(mx.y, v.y);
        mx.z = fmaxf(mx.z, v.z);
        mx.w = fmaxf(mx.w, v.w);
    }
    float4 u  = *(const float4*)(g_u3 + i*128 + lane*4);
    float4 bb = *(const float4*)(b3 + lane*4);
    float4 o;
    o.x = bb.x + u.x + mx.x;
    o.y = bb.y + u.y + mx.y;
    o.z = bb.z + u.z + mx.z;
    o.w = bb.w + u.w + mx.w;
    *(float4*)(g_x3 + i*128 + lane*4) = o;
}

// ---------------- init pool buffer ------------------------------------------
__global__ void init_out2_kernel(){
    int t = blockIdx.x*blockDim.x + threadIdx.x;
    if (t < B_*1024) g_out2[t] = -FLT_MAX;
}

// ---------------- lin1 (256->1024) fused with global max pool --------------
__global__ __launch_bounds__(256) void lin1max_kernel(
    const float* __restrict__ l1w, const float* __restrict__ l1b)
{
    __shared__ float fbuf[64*33];
    __shared__ float wbuf[32*132];
    int g     = blockIdx.x >> 5;
    int nbase = g*NPER + (blockIdx.x & 31)*64;
    int tn = threadIdx.x & 15, to = threadIdx.x >> 4;

    for (int oc=0; oc<8; ++oc){
        float acc[4][8];
        #pragma unroll
        for (int r=0;r<4;r++)
            #pragma unroll
            for (int q=0;q<8;q++) acc[r][q]=0.f;

        for (int kc=0;kc<8;kc++){
            for (int t=threadIdx.x; t<64*32; t+=256){
                int n = t>>5, kk = t&31;
                int kglob = kc*32+kk;
                int node  = nbase + n;
                float v;
                if (kglob < 64)       v = g_x1[node*64  + kglob];
                else if (kglob < 128) v = g_x2[node*64  + (kglob-64)];
                else                  v = g_x3[node*128 + (kglob-128)];
                fbuf[n*33+kk] = v;
            }
            for (int t=threadIdx.x; t<32*128; t+=256){
                int kk = t>>7, o = t&127;
                wbuf[kk*132+o] = l1w[(kc*32+kk)*1024 + oc*128 + o];
            }
            __syncthreads();
            #pragma unroll 4
            for (int kk=0;kk<32;kk++){
                float f0 = fbuf[(tn +  0)*33+kk];
                float f1 = fbuf[(tn + 16)*33+kk];
                float f2 = fbuf[(tn + 32)*33+kk];
                float f3 = fbuf[(tn + 48)*33+kk];
                float wv[8];
                #pragma unroll
                for (int q=0;q<8;q++) wv[q] = wbuf[kk*132 + to + 16*q];
                #pragma unroll
                for (int q=0;q<8;q++){
                    acc[0][q] += f0*wv[q];
                    acc[1][q] += f1*wv[q];
                    acc[2][q] += f2*wv[q];
                    acc[3][q] += f3*wv[q];
                }
            }
            __syncthreads();
        }
        float m[8];
        #pragma unroll
        for (int q=0;q<8;q++)
            m[q] = fmaxf(fmaxf(acc[0][q],acc[1][q]), fmaxf(acc[2][q],acc[3][q]));
        #pragma unroll
        for (int q=0;q<8;q++) wbuf[tn*128 + to + 16*q] = m[q];
        __syncthreads();
        if (threadIdx.x < 128){
            int c = threadIdx.x;
            float v = wbuf[c];
            #pragma unroll
            for (int t=1;t<16;t++) v = fmaxf(v, wbuf[t*128+c]);
            v += l1b[oc*128+c];
            atomicMaxFloat(&g_out2[g*1024 + oc*128 + c], v);
        }
        __syncthreads();
    }
}

// ---------------- head: MLP(1024->512->256->10) + log_softmax --------------
__global__ __launch_bounds__(256) void head_kernel(
    const float* __restrict__ m1w, const float* __restrict__ m1b,
    const float* __restrict__ m2w, const float* __restrict__ m2b,
    const float* __restrict__ m3w, const float* __restrict__ m3b,
    float* __restrict__ out)
{
    __shared__ float v[1024];
    __shared__ float h1[512];
    __shared__ float h2[256];
    __shared__ float z[10];
    int g = blockIdx.x;
    for (int t=threadIdx.x; t<1024; t+=256) v[t] = g_out2[g*1024+t];
    __syncthreads();
    #pragma unroll
    for (int oo=0;oo<2;oo++){
        int o = threadIdx.x + oo*256;
        float a = m1b[o];
        #pragma unroll 4
        for (int k=0;k<1024;k++) a += v[k]*m1w[k*512+o];
        h1[o] = fmaxf(a, 0.f);
    }
    __syncthreads();
    {
        int o = threadIdx.x;
        float a = m2b[o];
        #pragma unroll 4
        for (int k=0;k<512;k++) a += h1[k]*m2w[k*256+o];
        h2[o] = fmaxf(a, 0.f);
    }
    __syncthreads();
    if (threadIdx.x < 10){
        float a = m3b[threadIdx.x];
        for (int k=0;k<256;k++) a += h2[k]*m3w[k*10+threadIdx.x];
        z[threadIdx.x] = a;
    }
    __syncthreads();
    if (threadIdx.x == 0){
        float m = -FLT_MAX;
        for (int c=0;c<10;c++) m = fmaxf(m, z[c]);
        float s = 0.f;
        for (int c=0;c<10;c++) s += expf(z[c]-m);
        float l = logf(s);
        for (int c=0;c<10;c++) out[g*10+c] = z[c]-m-l;
    }
}

// ---------------- launch ----------------------------------------------------
extern "C" void kernel_launch(void* const* d_in, const int* in_sizes, int n_in,
                              void* d_out, int out_size)
{
    const float* pos  = (const float*)d_in[0];
    const float* xf   = (const float*)d_in[1];
    // d_in[2] = batch (implied by layout, unused)
    const float* c1w1 = (const float*)d_in[3];
    const float* c1b1 = (const float*)d_in[4];
    const float* c1w2 = (const float*)d_in[5];
    const float* c1b2 = (const float*)d_in[6];
    const float* c1w3 = (const float*)d_in[7];
    const float* c1b3 = (const float*)d_in[8];
    const float* c2w  = (const float*)d_in[9];
    const float* c2b  = (const float*)d_in[10];
    const float* c3w  = (const float*)d_in[11];
    const float* c3b  = (const float*)d_in[12];
    const float* l1w  = (const float*)d_in[13];
    const float* l1b  = (const float*)d_in[14];
    const float* m1w  = (const float*)d_in[15];
    const float* m1b  = (const float*)d_in[16];
    const float* m2w  = (const float*)d_in[17];
    const float* m2b  = (const float*)d_in[18];
    const float* m3w  = (const float*)d_in[19];
    const float* m3b  = (const float*)d_in[20];
    float* out = (float*)d_out;

    knn_kernel<<<B_*8, 256>>>(pos, xf);
    conv1_kernel<<<NTOT/8, 256>>>(c1w1,c1b1,c1w2,c1b2,c1w3,c1b3);
    uy_gemm2_kernel<<<dim3(NTOT/64, 1), 256>>>(c2w);
    gathermax2_kernel<<<NTOT/8, 256>>>(c2b);
    uy_gemm3_kernel<<<dim3(NTOT/64, 2), 256>>>(c3w);
    gathermax3_kernel<<<NTOT/8, 256>>>(c3b);
    init_out2_kernel<<<(B_*1024+255)/256, 256>>>();
    lin1max_kernel<<<B_*32, 256>>>(l1w, l1b);
    head_kernel<<<B_, 256>>>(m1w,m1b,m2w,m2b,m3w,m3b,out);
}

// round 5
// speedup vs baseline: 1.4823x; 1.2076x over previous
#include <cuda_runtime.h>
#include <cfloat>
#include <math.h>

#define B_   16
#define NPER 2048
#define NTOT (B_*NPER)
#define KNN  20

// ---------------- scratch (device globals; no runtime allocation) ----------
__device__ float4 g_x0[NTOT];            // [N][4]  concat(pos, x)
__device__ float  g_sn[NTOT];            // squared norms
__device__ int    g_idx[NTOT*KNN];       // [N][20] global neighbor indices
__device__ float  g_x1[NTOT*64];
__device__ float  g_x2[NTOT*64];
__device__ float  g_x3[NTOT*128];
__device__ float  g_u2[NTOT*64];         // x1 @ (W2_top - W2_bot)
__device__ float  g_y2[NTOT*64];         // x1 @ W2_bot
__device__ float  g_u3[NTOT*128];        // x2 @ (W3_top - W3_bot)
__device__ float  g_y3[NTOT*128];        // x2 @ W3_bot
__device__ float  g_out2[B_*1024];       // global max pool result

__device__ __forceinline__ void atomicMaxFloat(float* addr, float v){
    if (v >= 0.f) atomicMax((int*)addr, __float_as_int(v));
    else          atomicMin((unsigned int*)addr, (unsigned int)__float_as_int(v));
}

// packed f32x2 FMA (Blackwell): d = a*b + d elementwise on packed pairs
#define FMA2(d,a,b) asm("fma.rn.f32x2 %0, %1, %2, %0;" : "+l"(d) : "l"(a), "l"(b))

__device__ __forceinline__ unsigned long long dup2(float x){
    unsigned long long r; unsigned u = __float_as_uint(x);
    asm("mov.b64 %0, {%1, %1};" : "=l"(r) : "r"(u));
    return r;
}

// ---------------- prep kernels (also position knn at profiled launch #3) ---
__global__ __launch_bounds__(256) void x0_kernel(const float* __restrict__ pos,
                                                 const float* __restrict__ xf){
    int i = blockIdx.x*256 + threadIdx.x;
    g_x0[i] = make_float4(pos[i*3+0], pos[i*3+1], pos[i*3+2], xf[i]);
}
__global__ __launch_bounds__(256) void sn_kernel(){
    int i = blockIdx.x*256 + threadIdx.x;
    float4 p = g_x0[i];
    g_sn[i] = p.x*p.x + p.y*p.y + p.z*p.z + p.w*p.w;
}
__global__ void init_out2_kernel(){
    int t = blockIdx.x*blockDim.x + threadIdx.x;
    if (t < B_*1024) g_out2[t] = -FLT_MAX;
}

// ---------------- kNN: one thread per query, register-resident top-20 ------
__global__ __launch_bounds__(256) void knn_kernel()
{
    __shared__ float4 sp[NPER];
    __shared__ float  sn[NPER];
    int b     = blockIdx.x >> 3;
    int qbase = (blockIdx.x & 7) << 8;
    int base  = b * NPER;
    for (int j = threadIdx.x; j < NPER; j += 256){
        sp[j] = g_x0[base+j];
        sn[j] = g_sn[base+j];
    }
    __syncthreads();

    int q = qbase + (int)threadIdx.x;
    float4 p = sp[q];
    float  pn = sn[q];

    // distinct huge sentinels so "replace slot == worst" hits exactly one slot
    float bd[KNN]; int bi[KNN];
    #pragma unroll
    for (int t=0;t<KNN;t++){ bd[t] = __uint_as_float(0x7F7FFFFFu - (unsigned)t); bi[t]=0; }
    float worst = bd[0];   // = FLT_MAX

    for (int j=0;j<NPER;j++){
        float4 c = sp[j];
        float d = pn + sn[j] - 2.f*(p.x*c.x + p.y*c.y + p.z*c.z + p.w*c.w);
        if (d < worst && j != q){
            // replace the slot holding the current worst (values distinct a.s.)
            #pragma unroll
            for (int t=0;t<KNN;t++){
                if (bd[t] == worst){ bd[t] = d; bi[t] = j; }
            }
            // recompute worst via explicit max tree (static indexing only)
            float tm[KNN];
            #pragma unroll
            for (int t=0;t<KNN;t++) tm[t] = bd[t];
            #pragma unroll
            for (int s=1;s<KNN;s<<=1){
                #pragma unroll
                for (int t=0;t+s<KNN;t+=(s<<1)) tm[t] = fmaxf(tm[t], tm[t+s]);
            }
            worst = tm[0];
        }
    }
    #pragma unroll
    for (int t=0;t<KNN;t++) g_idx[(base+q)*KNN + t] = base + bi[t];
}

// ---------------- EdgeConv1: fused MLP(8->64->64->64), max over K ----------
__global__ __launch_bounds__(256) void conv1_kernel(
    const float* __restrict__ w1, const float* __restrict__ b1,
    const float* __restrict__ w2, const float* __restrict__ b2,
    const float* __restrict__ w3, const float* __restrict__ b3)
{
    __shared__ float sW1 [4*64];
    __shared__ float sW1d[4*64];
    __shared__ float sW2t[64*68];
    __shared__ float sW3t[64*68];
    __shared__ float sb1[64], sb2[64], sb3[64];
    __shared__ float hbuf[8][4][64];

    for (int t = threadIdx.x; t < 64*64; t += 256){
        int c = t >> 6, o = t & 63;
        sW2t[o*68+c] = w2[t];
        sW3t[o*68+c] = w3[t];
    }
    for (int t = threadIdx.x; t < 4*64; t += 256){
        int c = t >> 6, o = t & 63;
        float top = w1[c*64+o], bot = w1[(c+4)*64+o];
        sW1[t] = bot; sW1d[t] = top - bot;
    }
    if (threadIdx.x < 64){
        sb1[threadIdx.x] = b1[threadIdx.x];
        sb2[threadIdx.x] = b2[threadIdx.x];
        sb3[threadIdx.x] = b3[threadIdx.x];
    }
    __syncthreads();

    int wd = threadIdx.x >> 5, lane = threadIdx.x & 31;
    int i  = blockIdx.x * 8 + wd;
    int o0 = lane, o1 = lane + 32;
    float4 xi = g_x0[i];
    float base0 = sb1[o0] + xi.x*sW1d[o0] + xi.y*sW1d[64+o0] + xi.z*sW1d[128+o0] + xi.w*sW1d[192+o0];
    float base1 = sb1[o1] + xi.x*sW1d[o1] + xi.y*sW1d[64+o1] + xi.z*sW1d[128+o1] + xi.w*sW1d[192+o1];
    float mx0 = -FLT_MAX, mx1 = -FLT_MAX;
    const int* ip = g_idx + i*KNN;

    for (int kg = 0; kg < 5; kg++){
        #pragma unroll
        for (int e=0;e<4;e++){
            int j = ip[kg*4+e];
            float4 xj = g_x0[j];
            float v0 = base0 + xj.x*sW1[o0] + xj.y*sW1[64+o0] + xj.z*sW1[128+o0] + xj.w*sW1[192+o0];
            float v1 = base1 + xj.x*sW1[o1] + xj.y*sW1[64+o1] + xj.z*sW1[128+o1] + xj.w*sW1[192+o1];
            hbuf[wd][e][o0] = fmaxf(v0, 0.f);
            hbuf[wd][e][o1] = fmaxf(v1, 0.f);
        }
        __syncwarp();
        float a0[4], a1[4];
        #pragma unroll
        for (int e=0;e<4;e++){ a0[e]=sb2[o0]; a1[e]=sb2[o1]; }
        #pragma unroll
        for (int c4=0;c4<16;c4++){
            float4 wv0 = *(const float4*)(sW2t + o0*68 + c4*4);
            float4 wv1 = *(const float4*)(sW2t + o1*68 + c4*4);
            #pragma unroll
            for (int e=0;e<4;e++){
                float4 h = *(const float4*)(&hbuf[wd][e][c4*4]);
                a0[e] += h.x*wv0.x + h.y*wv0.y + h.z*wv0.z + h.w*wv0.w;
                a1[e] += h.x*wv1.x + h.y*wv1.y + h.z*wv1.z + h.w*wv1.w;
            }
        }
        __syncwarp();
        #pragma unroll
        for (int e=0;e<4;e++){
            hbuf[wd][e][o0] = fmaxf(a0[e], 0.f);
            hbuf[wd][e][o1] = fmaxf(a1[e], 0.f);
        }
        __syncwarp();
        #pragma unroll
        for (int e=0;e<4;e++){ a0[e]=sb3[o0]; a1[e]=sb3[o1]; }
        #pragma unroll
        for (int c4=0;c4<16;c4++){
            float4 wv0 = *(const float4*)(sW3t + o0*68 + c4*4);
            float4 wv1 = *(const float4*)(sW3t + o1*68 + c4*4);
            #pragma unroll
            for (int e=0;e<4;e++){
                float4 h = *(const float4*)(&hbuf[wd][e][c4*4]);
                a0[e] += h.x*wv0.x + h.y*wv0.y + h.z*wv0.z + h.w*wv0.w;
                a1[e] += h.x*wv1.x + h.y*wv1.y + h.z*wv1.z + h.w*wv1.w;
            }
        }
        #pragma unroll
        for (int e=0;e<4;e++){ mx0 = fmaxf(mx0, a0[e]); mx1 = fmaxf(mx1, a1[e]); }
        __syncwarp();
    }
    g_x1[i*64+o0] = mx0;
    g_x1[i*64+o1] = mx1;
}

// ---------------- node-level GEMM: U = X@(Wt-Wb), Y = X@Wb ------------------
__device__ __forceinline__ void uy_gemm_body(
    const float* __restrict__ X,   // [N x 64]
    const float* __restrict__ W,   // [128 x OUT]
    float* __restrict__ U, float* __restrict__ Y, int OUT)
{
    __shared__ float fbuf[64*33];
    __shared__ float wbuf[32*132];
    int nbase = blockIdx.x * 64;
    int otile = blockIdx.y * 128;
    int tn = threadIdx.x & 15;
    int to = threadIdx.x >> 4;

    float acc[4][8];
    #pragma unroll
    for (int r=0;r<4;r++)
        #pragma unroll
        for (int q=0;q<8;q++) acc[r][q]=0.f;

    for (int kc=0;kc<2;kc++){
        for (int t=threadIdx.x; t<64*32; t+=256){
            int n=t>>5, kk=t&31;
            fbuf[n*33+kk] = X[(nbase+n)*64 + kc*32 + kk];
        }
        for (int t=threadIdx.x; t<32*128; t+=256){
            int kk=t>>7, oloc=t&127;
            int op = otile + oloc;
            int k  = kc*32+kk;
            wbuf[kk*132+oloc] = (op < OUT)
                ? (W[k*OUT + op] - W[(64+k)*OUT + op])
                : W[(64+k)*OUT + (op-OUT)];
        }
        __syncthreads();
        #pragma unroll 4
        for (int kk=0;kk<32;kk++){
            float f[4];
            #pragma unroll
            for (int r=0;r<4;r++) f[r] = fbuf[(to+16*r)*33+kk];
            float wv[8];
            #pragma unroll
            for (int q=0;q<8;q++) wv[q] = wbuf[kk*132 + tn + 16*q];
            #pragma unroll
            for (int r=0;r<4;r++)
                #pragma unroll
                for (int q=0;q<8;q++) acc[r][q] += f[r]*wv[q];
        }
        __syncthreads();
    }
    #pragma unroll
    for (int r=0;r<4;r++){
        int node = nbase + to + 16*r;
        #pragma unroll
        for (int q=0;q<8;q++){
            int op = otile + tn + 16*q;
            if (op < OUT) U[node*OUT + op]        = acc[r][q];
            else          Y[node*OUT + (op-OUT)]  = acc[r][q];
        }
    }
}

__global__ __launch_bounds__(256) void uy_gemm2_kernel(const float* __restrict__ W){
    uy_gemm_body(g_x1, W, g_u2, g_y2, 64);
}
__global__ __launch_bounds__(256) void uy_gemm3_kernel(const float* __restrict__ W){
    uy_gemm_body(g_x2, W, g_u3, g_y3, 128);
}

// ---------------- gather + elementwise max ----------------------------------
__global__ __launch_bounds__(256) void gathermax2_kernel(const float* __restrict__ b2){
    int wd = threadIdx.x >> 5, lane = threadIdx.x & 31;
    int i = blockIdx.x*8 + wd;
    const int* ip = g_idx + i*KNN;
    float2 mx = make_float2(-FLT_MAX, -FLT_MAX);
    #pragma unroll 5
    for (int t=0;t<KNN;t++){
        int j = ip[t];
        float2 v = *(const float2*)(g_y2 + j*64 + lane*2);
        mx.x = fmaxf(mx.x, v.x);
        mx.y = fmaxf(mx.y, v.y);
    }
    float2 u  = *(const float2*)(g_u2 + i*64 + lane*2);
    float2 bb = *(const float2*)(b2 + lane*2);
    float2 o;
    o.x = bb.x + u.x + mx.x;
    o.y = bb.y + u.y + mx.y;
    *(float2*)(g_x2 + i*64 + lane*2) = o;
}

__global__ __launch_bounds__(256) void gathermax3_kernel(const float* __restrict__ b3){
    int wd = threadIdx.x >> 5, lane = threadIdx.x & 31;
    int i = blockIdx.x*8 + wd;
    const int* ip = g_idx + i*KNN;
    float4 mx = make_float4(-FLT_MAX,-FLT_MAX,-FLT_MAX,-FLT_MAX);
    #pragma unroll 5
    for (int t=0;t<KNN;t++){
        int j = ip[t];
        float4 v = *(const float4*)(g_y3 + j*128 + lane*4);
        mx.x = fmaxf(mx.x, v.x);
        mx.y = fmaxf(mx.y, v.y);
        mx.z = fmaxf(mx.z, v.z);
        mx.w = fmaxf(mx.w, v.w);
    }
    float4 u  = *(const float4*)(g_u3 + i*128 + lane*4);
    float4 bb = *(const float4*)(b3 + lane*4);
    float4 o;
    o.x = bb.x + u.x + mx.x;
    o.y = bb.y + u.y + mx.y;
    o.z = bb.z + u.z + mx.z;
    o.w = bb.w + u.w + mx.w;
    *(float4*)(g_x3 + i*128 + lane*4) = o;
}

// ---------------- lin1 (256->1024) fused with global max pool, f32x2 -------
// 64-node tile, 256-out chunks (oc loop 4). Thread: tn=tid&31 -> outs tn*8+q,
// to=tid>>5 -> nodes to*8+r. Node pairs packed straight from LDS.128.
__global__ __launch_bounds__(256) void lin1max_kernel(
    const float* __restrict__ l1w, const float* __restrict__ l1b)
{
    __shared__ float fbufT[32*68];       // [kk][node]
    __shared__ float wbuf[32*260];       // [kk][o] (o < 256)
    int g     = blockIdx.x >> 5;
    int nbase = g*NPER + (blockIdx.x & 31)*64;
    int tn = threadIdx.x & 31;
    int to = threadIdx.x >> 5;

    for (int oc=0; oc<4; ++oc){
        unsigned long long acc2[4][8];   // [node-pair][q]
        #pragma unroll
        for (int np=0;np<4;np++)
            #pragma unroll
            for (int q=0;q<8;q++) acc2[np][q] = 0ull;

        for (int kc=0;kc<8;kc++){
            for (int t=threadIdx.x; t<64*32; t+=256){
                int n = t>>5, kk = t&31;
                int kglob = kc*32+kk;
                int node  = nbase + n;
                float v;
                if (kglob < 64)       v = g_x1[node*64  + kglob];
                else if (kglob < 128) v = g_x2[node*64  + (kglob-64)];
                else                  v = g_x3[node*128 + (kglob-128)];
                fbufT[kk*68+n] = v;
            }
            for (int t=threadIdx.x; t<32*256; t+=256){
                int kk = t>>8, o = t&255;
                wbuf[kk*260+o] = l1w[(kc*32+kk)*1024 + oc*256 + o];
            }
            __syncthreads();
            #pragma unroll 4
            for (int kk=0;kk<32;kk++){
                // 8 nodes as 4 packed pairs (broadcast within warp: same 'to')
                ulonglong2 fA = *(const ulonglong2*)(fbufT + kk*68 + to*8);
                ulonglong2 fB = *(const ulonglong2*)(fbufT + kk*68 + to*8 + 4);
                // 8 weights, dup-packed
                float4 wA = *(const float4*)(wbuf + kk*260 + tn*8);
                float4 wB = *(const float4*)(wbuf + kk*260 + tn*8 + 4);
                unsigned long long wd0 = dup2(wA.x), wd1 = dup2(wA.y);
                unsigned long long wd2 = dup2(wA.z), wd3 = dup2(wA.w);
                unsigned long long wd4 = dup2(wB.x), wd5 = dup2(wB.y);
                unsigned long long wd6 = dup2(wB.z), wd7 = dup2(wB.w);
                unsigned long long fp[4] = {fA.x, fA.y, fB.x, fB.y};
                #pragma unroll
                for (int np=0;np<4;np++){
                    FMA2(acc2[np][0], fp[np], wd0);
                    FMA2(acc2[np][1], fp[np], wd1);
                    FMA2(acc2[np][2], fp[np], wd2);
                    FMA2(acc2[np][3], fp[np], wd3);
                    FMA2(acc2[np][4], fp[np], wd4);
                    FMA2(acc2[np][5], fp[np], wd5);
                    FMA2(acc2[np][6], fp[np], wd6);
                    FMA2(acc2[np][7], fp[np], wd7);
                }
            }
            __syncthreads();
        }
        // epilogue: max over this thread's 8 nodes, then over node groups
        float m[8];
        #pragma unroll
        for (int q=0;q<8;q++){
            float best = -FLT_MAX;
            #pragma unroll
            for (int np=0;np<4;np++){
                unsigned lo, hi;
                asm("mov.b64 {%0, %1}, %2;" : "=r"(lo), "=r"(hi) : "l"(acc2[np][q]));
                best = fmaxf(best, fmaxf(__uint_as_float(lo), __uint_as_float(hi)));
            }
            m[q] = best;
        }
        #pragma unroll
        for (int q=0;q<8;q++) wbuf[to*260 + tn*8 + q] = m[q];
        __syncthreads();
        {
            int o = threadIdx.x;     // 0..255
            float v = wbuf[o];
            #pragma unroll
            for (int t2=1;t2<8;t2++) v = fmaxf(v, wbuf[t2*260 + o]);
            v += l1b[oc*256 + o];
            atomicMaxFloat(&g_out2[g*1024 + oc*256 + o], v);
        }
        __syncthreads();
    }
}

// ---------------- head: MLP(1024->512->256->10) + log_softmax --------------
__global__ __launch_bounds__(256) void head_kernel(
    const float* __restrict__ m1w, const float* __restrict__ m1b,
    const float* __restrict__ m2w, const float* __restrict__ m2b,
    const float* __restrict__ m3w, const float* __restrict__ m3b,
    float* __restrict__ out)
{
    __shared__ float v[1024];
    __shared__ float h1[512];
    __shared__ float h2[256];
    __shared__ float z[10];
    int g = blockIdx.x;
    for (int t=threadIdx.x; t<1024; t+=256) v[t] = g_out2[g*1024+t];
    __syncthreads();
    #pragma unroll
    for (int oo=0;oo<2;oo++){
        int o = threadIdx.x + oo*256;
        float a = m1b[o];
        #pragma unroll 4
        for (int k=0;k<1024;k++) a += v[k]*m1w[k*512+o];
        h1[o] = fmaxf(a, 0.f);
    }
    __syncthreads();
    {
        int o = threadIdx.x;
        float a = m2b[o];
        #pragma unroll 4
        for (int k=0;k<512;k++) a += h1[k]*m2w[k*256+o];
        h2[o] = fmaxf(a, 0.f);
    }
    __syncthreads();
    if (threadIdx.x < 10){
        float a = m3b[threadIdx.x];
        for (int k=0;k<256;k++) a += h2[k]*m3w[k*10+threadIdx.x];
        z[threadIdx.x] = a;
    }
    __syncthreads();
    if (threadIdx.x == 0){
        float m = -FLT_MAX;
        for (int c=0;c<10;c++) m = fmaxf(m, z[c]);
        float s = 0.f;
        for (int c=0;c<10;c++) s += expf(z[c]-m);
        float l = logf(s);
        for (int c=0;c<10;c++) out[g*10+c] = z[c]-m-l;
    }
}

// ---------------- launch ----------------------------------------------------
extern "C" void kernel_launch(void* const* d_in, const int* in_sizes, int n_in,
                              void* d_out, int out_size)
{
    const float* pos  = (const float*)d_in[0];
    const float* xf   = (const float*)d_in[1];
    const float* c1w1 = (const float*)d_in[3];
    const float* c1b1 = (const float*)d_in[4];
    const float* c1w2 = (const float*)d_in[5];
    const float* c1b2 = (const float*)d_in[6];
    const float* c1w3 = (const float*)d_in[7];
    const float* c1b3 = (const float*)d_in[8];
    const float* c2w  = (const float*)d_in[9];
    const float* c2b  = (const float*)d_in[10];
    const float* c3w  = (const float*)d_in[11];
    const float* c3b  = (const float*)d_in[12];
    const float* l1w  = (const float*)d_in[13];
    const float* l1b  = (const float*)d_in[14];
    const float* m1w  = (const float*)d_in[15];
    const float* m1b  = (const float*)d_in[16];
    const float* m2w  = (const float*)d_in[17];
    const float* m2b  = (const float*)d_in[18];
    const float* m3w  = (const float*)d_in[19];
    const float* m3b  = (const float*)d_in[20];
    float* out = (float*)d_out;

    x0_kernel<<<NTOT/256, 256>>>(pos, xf);          // launch 0
    sn_kernel<<<NTOT/256, 256>>>();                 // launch 1
    init_out2_kernel<<<(B_*1024+255)/256, 256>>>(); // launch 2
    knn_kernel<<<B_*8, 256>>>();                    // launch 3 (profiled)
    conv1_kernel<<<NTOT/8, 256>>>(c1w1,c1b1,c1w2,c1b2,c1w3,c1b3);
    uy_gemm2_kernel<<<dim3(NTOT/64, 1), 256>>>(c2w);
    gathermax2_kernel<<<NTOT/8, 256>>>(c2b);
    uy_gemm3_kernel<<<dim3(NTOT/64, 2), 256>>>(c3w);
    gathermax3_kernel<<<NTOT/8, 256>>>(c3b);
    lin1max_kernel<<<B_*32, 256>>>(l1w, l1b);
    head_kernel<<<B_, 256>>>(m1w,m1b,m2w,m2b,m3w,m3b,out);
}